// round 12
// baseline (speedup 1.0000x reference)
#include <cuda_runtime.h>
#include <cuda_bf16.h>

// Problem constants (fixed by the reference)
static constexpr int BN = 262144;   // batch (2^18)
static constexpr int KN = 3;        // centers per class
static constexpr int DN = 64;       // feature dim
static constexpr float TH_F  = 0.95f;
static constexpr float EPS_F = 1e-12f;

static constexpr int GRID   = 2048;                 // 2048*8 = 16384 warps
static constexpr int NWARPS = GRID * 256 / 32;      // 16384
static constexpr int ITERS  = BN / 4 / NWARPS;      // 4 row-groups per warp

// Global accumulators (zero-initialized at module load; reset by last block each run)
__device__ double g_sum_min    = 0.0;
__device__ double g_sum_masked = 0.0;
__device__ double g_cnt        = 0.0;
__device__ unsigned int g_done = 0u;

__device__ __forceinline__ float dist4(const float4 a, const float4 b) {
    const float d0 = a.x - b.x, d1 = a.y - b.y;
    const float d2 = a.z - b.z, d3 = a.w - b.w;
    return d0 * d0 + d1 * d1 + d2 * d2 + d3 * d3;
}

// R5 body (best known: 25.1us) with __launch_bounds__(256, 8):
// forces 32 regs -> 64 warps/SM theoretical occupancy. The kernel is
// latency-exposure bound; R2 showed occ 80% -> issue 68% on this access
// pattern. 8 lanes/row, 4 rows/warp-iter, 4 iters/warp.
__global__ void __launch_bounds__(256, 8)
dist_kernel(const float4* __restrict__ x4,
            const int*    __restrict__ labels,
            const float4* __restrict__ c4,
            float*        __restrict__ out)
{
    const int lane    = threadIdx.x & 31;
    const int r       = lane >> 3;       // row within group (0..3)
    const int s       = lane & 7;        // float4 slot within 128B half-row
    const int warp_id = (blockIdx.x * blockDim.x + threadIdx.x) >> 5;

    // Prefetch all labels (independent loads, resolve while x streams in)
    int labs[ITERS];
    #pragma unroll
    for (int it = 0; it < ITERS; it++) {
        const int row = (warp_id + it * NWARPS) * 4 + r;
        labs[it] = __ldg(&labels[row]);
    }

    float acc_min = 0.f, acc_msk = 0.f, acc_cnt = 0.f;

    #pragma unroll
    for (int it = 0; it < ITERS; it++) {
        const int grp = warp_id + it * NWARPS;
        const int row = grp * 4 + r;

        // x: 2 float4 per lane; warp LDG = 4 rows x 128B contiguous (dense)
        const float4* xb = x4 + (size_t)row * 16 + s;
        const float4 xv0 = __ldcs(xb + 0);
        const float4 xv1 = __ldcs(xb + 8);

        const float4* cb = c4 + (size_t)labs[it] * (KN * (DN / 4)) + s;

        // 3 centers x 2 half-rows; every warp LDG covers 4 full 128B lines
        const float4 c00 = __ldg(cb + 0);
        const float4 c01 = __ldg(cb + 8);
        const float4 c10 = __ldg(cb + 16);
        const float4 c11 = __ldg(cb + 24);
        const float4 c20 = __ldg(cb + 32);
        const float4 c21 = __ldg(cb + 40);

        float p0 = dist4(xv0, c00) + dist4(xv1, c01);
        float p1 = dist4(xv0, c10) + dist4(xv1, c11);
        float p2 = dist4(xv0, c20) + dist4(xv1, c21);

        // Reduce within the 8-lane group (xor 1,2,4 never crosses groups)
        #pragma unroll
        for (int o = 1; o < 8; o <<= 1) {
            p0 += __shfl_xor_sync(0xffffffffu, p0, o);
            p1 += __shfl_xor_sync(0xffffffffu, p1, o);
            p2 += __shfl_xor_sync(0xffffffffu, p2, o);
        }

        if (s == 0) {
            // two smallest of three + min
            const float mn  = fminf(fminf(p0, p1), p2);
            const float mx  = fmaxf(fmaxf(p0, p1), p2);
            const float mid = (p0 + p1 + p2) - mn - mx;

            const float a = mn  + EPS_F;
            const float b = mid + EPS_F;
            const float p = a / (a + b);                  // 0 < p <= 0.5
            const float ent = -(p * log2f(p) + (1.f - p) * log2f(1.f - p));

            acc_min += mn;
            if (ent <= TH_F) { acc_msk += mn; acc_cnt += 1.f; }
        }
    }

    // Warp reduce (only s==0 lanes carry nonzero values)
    #pragma unroll
    for (int o = 16; o > 0; o >>= 1) {
        acc_min += __shfl_xor_sync(0xffffffffu, acc_min, o);
        acc_msk += __shfl_xor_sync(0xffffffffu, acc_msk, o);
        acc_cnt += __shfl_xor_sync(0xffffffffu, acc_cnt, o);
    }

    // Block reduce + one double atomic triple per block
    __shared__ float sm[3][8];
    __shared__ bool  s_last;
    const int wib = threadIdx.x >> 5;
    if (lane == 0) { sm[0][wib] = acc_min; sm[1][wib] = acc_msk; sm[2][wib] = acc_cnt; }
    __syncthreads();

    if (threadIdx.x == 0) {
        float a = 0.f, b = 0.f, c = 0.f;
        #pragma unroll
        for (int i = 0; i < 8; i++) { a += sm[0][i]; b += sm[1][i]; c += sm[2][i]; }
        atomicAdd(&g_sum_min,    (double)a);
        atomicAdd(&g_sum_masked, (double)b);
        atomicAdd(&g_cnt,        (double)c);
        __threadfence();
        const unsigned int ticket = atomicAdd(&g_done, 1u);
        s_last = (ticket == (unsigned int)(GRID - 1));
    }
    __syncthreads();

    // Last block: produce outputs and reset state for the next graph replay
    if (s_last && threadIdx.x == 0) {
        __threadfence();
        const double smn = g_sum_min;
        const double smk = g_sum_masked;
        const double cnt = g_cnt;
        out[0] = (float)(smn / (double)BN);
        out[1] = (float)(smk / cnt);
        g_sum_min = 0.0; g_sum_masked = 0.0; g_cnt = 0.0;
        __threadfence();
        g_done = 0u;
    }
}

extern "C" void kernel_launch(void* const* d_in, const int* in_sizes, int n_in,
                              void* d_out, int out_size) {
    const float* x       = (const float*)d_in[0];   // [B, D] f32
    const int*   labels  = (const int*)  d_in[1];   // [B] i32
    const float* centers = (const float*)d_in[2];   // [C, K, D] f32

    dist_kernel<<<GRID, 256>>>((const float4*)x, labels,
                               (const float4*)centers, (float*)d_out);
}

// round 13
// speedup vs baseline: 1.4817x; 1.4817x over previous
#include <cuda_runtime.h>
#include <cuda_bf16.h>

// Problem constants (fixed by the reference)
static constexpr int BN = 262144;   // batch (2^18)
static constexpr int KN = 3;        // centers per class
static constexpr int DN = 64;       // feature dim
static constexpr float TH_F  = 0.95f;
static constexpr float EPS_F = 1e-12f;

static constexpr int GRID      = 2048;
static constexpr int ROWS_ITER = 32;                      // rows per block-iteration
static constexpr int ITERS     = BN / (GRID * ROWS_ITER); // 4
static constexpr int F4_ITER   = ROWS_ITER * (DN / 4);    // 512 float4 per stage (8KB)

// Global accumulators (zero-initialized at module load; reset by last block each run)
__device__ double g_sum_min    = 0.0;
__device__ double g_sum_masked = 0.0;
__device__ double g_cnt        = 0.0;
__device__ unsigned int g_done = 0u;

__device__ __forceinline__ void cp_async16(void* smem_dst, const void* gmem_src) {
    unsigned sa = (unsigned)__cvta_generic_to_shared(smem_dst);
    asm volatile("cp.async.cg.shared.global [%0], [%1], 16;\n" :: "r"(sa), "l"(gmem_src));
}
__device__ __forceinline__ void cp_async_commit() {
    asm volatile("cp.async.commit_group;\n" ::: "memory");
}
template <int N>
__device__ __forceinline__ void cp_async_wait() {
    asm volatile("cp.async.wait_group %0;\n" :: "n"(N) : "memory");
}

__device__ __forceinline__ float dist4(const float4 a, const float4 b) {
    const float d0 = a.x - b.x, d1 = a.y - b.y;
    const float d2 = a.z - b.z, d3 = a.w - b.w;
    return d0 * d0 + d1 * d1 + d2 * d2 + d3 * d3;
}

// R5 body + ALL x stages queued via cp.async at t=0 (write-once buffers).
// By the time each iteration runs, its x data has been in flight for the whole
// preceding compute -> x DRAM latency fully hidden with zero register cost.
// Centers (L2, ~250cyc) consumed directly as in R5. 8 lanes/row, 4 rows/warp.
__global__ void __launch_bounds__(256)
dist_kernel(const float4* __restrict__ x4,
            const int*    __restrict__ labels,
            const float4* __restrict__ c4,
            float*        __restrict__ out)
{
    __shared__ float4 xbuf[ITERS][F4_ITER];   // 4 x 8KB = 32KB, each written once
    __shared__ float  sm[3][8];
    __shared__ bool   s_last;

    const int tid   = threadIdx.x;
    const int lane  = tid & 31;
    const int w     = tid >> 5;           // warp in block (0..7)
    const int r     = lane >> 3;          // row within warp group (0..3)
    const int s     = lane & 7;           // float4 slot within 128B half-row
    const int row_local = w * 4 + r;      // 0..31

    // ---- Prologue: queue ALL x stages (4 groups) + all labels ----
    #pragma unroll
    for (int it = 0; it < ITERS; it++) {
        const float4* xg = x4 + (size_t)(blockIdx.x + it * GRID) * F4_ITER;
        cp_async16(&xbuf[it][tid],       xg + tid);
        cp_async16(&xbuf[it][tid + 256], xg + tid + 256);
        cp_async_commit();
    }

    int labs[ITERS];
    #pragma unroll
    for (int it = 0; it < ITERS; it++) {
        const int base = (blockIdx.x + it * GRID) * ROWS_ITER;
        labs[it] = __ldg(&labels[base + row_local]);
    }

    float acc_min = 0.f, acc_msk = 0.f, acc_cnt = 0.f;

#define PROC_ITER(IT, WAITN)                                                   \
    {                                                                          \
        cp_async_wait<WAITN>();                                                \
        __syncthreads();                                                       \
        const float4* xs = xbuf[IT];                                           \
        const float4 xv0 = xs[row_local * 16 + s];                             \
        const float4 xv1 = xs[row_local * 16 + s + 8];                         \
        const float4* cb = c4 + (size_t)labs[IT] * (KN * (DN / 4)) + s;        \
        const float4 c00 = __ldg(cb + 0);                                      \
        const float4 c01 = __ldg(cb + 8);                                      \
        const float4 c10 = __ldg(cb + 16);                                     \
        const float4 c11 = __ldg(cb + 24);                                     \
        const float4 c20 = __ldg(cb + 32);                                     \
        const float4 c21 = __ldg(cb + 40);                                     \
        float p0 = dist4(xv0, c00) + dist4(xv1, c01);                          \
        float p1 = dist4(xv0, c10) + dist4(xv1, c11);                          \
        float p2 = dist4(xv0, c20) + dist4(xv1, c21);                          \
        _Pragma("unroll")                                                      \
        for (int o = 1; o < 8; o <<= 1) {                                      \
            p0 += __shfl_xor_sync(0xffffffffu, p0, o);                         \
            p1 += __shfl_xor_sync(0xffffffffu, p1, o);                         \
            p2 += __shfl_xor_sync(0xffffffffu, p2, o);                         \
        }                                                                      \
        if (s == 0) {                                                          \
            const float mn  = fminf(fminf(p0, p1), p2);                        \
            const float mx  = fmaxf(fmaxf(p0, p1), p2);                        \
            const float mid = (p0 + p1 + p2) - mn - mx;                        \
            const float a = mn  + EPS_F;                                       \
            const float b = mid + EPS_F;                                       \
            const float p = a / (a + b);                                       \
            const float ent = -(p * log2f(p) + (1.f - p) * log2f(1.f - p));    \
            acc_min += mn;                                                     \
            if (ent <= TH_F) { acc_msk += mn; acc_cnt += 1.f; }                \
        }                                                                      \
    }

    PROC_ITER(0, 3)
    PROC_ITER(1, 2)
    PROC_ITER(2, 1)
    PROC_ITER(3, 0)
#undef PROC_ITER

    // Warp reduce (only s==0 lanes carry nonzero values)
    #pragma unroll
    for (int o = 16; o > 0; o >>= 1) {
        acc_min += __shfl_xor_sync(0xffffffffu, acc_min, o);
        acc_msk += __shfl_xor_sync(0xffffffffu, acc_msk, o);
        acc_cnt += __shfl_xor_sync(0xffffffffu, acc_cnt, o);
    }

    if (lane == 0) { sm[0][w] = acc_min; sm[1][w] = acc_msk; sm[2][w] = acc_cnt; }
    __syncthreads();

    if (tid == 0) {
        float a = 0.f, b = 0.f, c = 0.f;
        #pragma unroll
        for (int i = 0; i < 8; i++) { a += sm[0][i]; b += sm[1][i]; c += sm[2][i]; }
        atomicAdd(&g_sum_min,    (double)a);
        atomicAdd(&g_sum_masked, (double)b);
        atomicAdd(&g_cnt,        (double)c);
        __threadfence();
        const unsigned int ticket = atomicAdd(&g_done, 1u);
        s_last = (ticket == (unsigned int)(GRID - 1));
    }
    __syncthreads();

    // Last block: produce outputs and reset state for the next graph replay
    if (s_last && tid == 0) {
        __threadfence();
        const double smn = g_sum_min;
        const double smk = g_sum_masked;
        const double cnt = g_cnt;
        out[0] = (float)(smn / (double)BN);
        out[1] = (float)(smk / cnt);
        g_sum_min = 0.0; g_sum_masked = 0.0; g_cnt = 0.0;
        __threadfence();
        g_done = 0u;
    }
}

extern "C" void kernel_launch(void* const* d_in, const int* in_sizes, int n_in,
                              void* d_out, int out_size) {
    const float* x       = (const float*)d_in[0];   // [B, D] f32
    const int*   labels  = (const int*)  d_in[1];   // [B] i32
    const float* centers = (const float*)d_in[2];   // [C, K, D] f32

    dist_kernel<<<GRID, 256>>>((const float4*)x, labels,
                               (const float4*)centers, (float*)d_out);
}

// round 14
// speedup vs baseline: 1.4987x; 1.0115x over previous
#include <cuda_runtime.h>
#include <cuda_bf16.h>

// Problem constants (fixed by the reference)
static constexpr int BN = 262144;   // batch (2^18)
static constexpr int KN = 3;        // centers per class
static constexpr int DN = 64;       // feature dim
static constexpr float TH_F  = 0.95f;
static constexpr float EPS_F = 1e-12f;

static constexpr int GRID   = 2048;                 // 2048*8 = 16384 warps
static constexpr int NWARPS = GRID * 256 / 32;      // 16384
static constexpr int ITERS  = BN / 4 / NWARPS;      // 4 row-groups per warp

// Global accumulators (zero-initialized at module load; reset by last block each run)
__device__ double g_sum_min    = 0.0;
__device__ double g_sum_masked = 0.0;
__device__ double g_cnt        = 0.0;
__device__ unsigned int g_done = 0u;

__device__ __forceinline__ float dist4(const float4 a, const float4 b) {
    const float d0 = a.x - b.x, d1 = a.y - b.y;
    const float d2 = a.z - b.z, d3 = a.w - b.w;
    return d0 * d0 + d1 * d1 + d2 * d2 + d3 * d3;
}

// R5 structure (best known) with the entropy block rewritten using fast-math
// intrinsics: __fdividef + __log2f. This collapses ~65 issued instructions and
// ~200 cycles of dependent div->log->log chain per warp-iteration down to ~8
// instructions / ~40 cycles. 8 lanes/row, 4 rows/warp-iter, 4 iters/warp.
__global__ void __launch_bounds__(256)
dist_kernel(const float4* __restrict__ x4,
            const int*    __restrict__ labels,
            const float4* __restrict__ c4,
            float*        __restrict__ out)
{
    const int lane    = threadIdx.x & 31;
    const int r       = lane >> 3;       // row within group (0..3)
    const int s       = lane & 7;        // float4 slot within 128B half-row
    const int warp_id = (blockIdx.x * blockDim.x + threadIdx.x) >> 5;

    // Prefetch all labels (independent loads, resolve while x streams in)
    int labs[ITERS];
    #pragma unroll
    for (int it = 0; it < ITERS; it++) {
        const int row = (warp_id + it * NWARPS) * 4 + r;
        labs[it] = __ldg(&labels[row]);
    }

    float acc_min = 0.f, acc_msk = 0.f, acc_cnt = 0.f;

    #pragma unroll
    for (int it = 0; it < ITERS; it++) {
        const int grp = warp_id + it * NWARPS;
        const int row = grp * 4 + r;

        // x: 2 float4 per lane; warp LDG = 4 rows x 128B contiguous (dense)
        const float4* xb = x4 + (size_t)row * 16 + s;
        const float4 xv0 = __ldcs(xb + 0);
        const float4 xv1 = __ldcs(xb + 8);

        const float4* cb = c4 + (size_t)labs[it] * (KN * (DN / 4)) + s;

        // 3 centers x 2 half-rows; every warp LDG covers 4 full 128B lines
        const float4 c00 = __ldg(cb + 0);
        const float4 c01 = __ldg(cb + 8);
        const float4 c10 = __ldg(cb + 16);
        const float4 c11 = __ldg(cb + 24);
        const float4 c20 = __ldg(cb + 32);
        const float4 c21 = __ldg(cb + 40);

        float p0 = dist4(xv0, c00) + dist4(xv1, c01);
        float p1 = dist4(xv0, c10) + dist4(xv1, c11);
        float p2 = dist4(xv0, c20) + dist4(xv1, c21);

        // Reduce within the 8-lane group (xor 1,2,4 never crosses groups)
        #pragma unroll
        for (int o = 1; o < 8; o <<= 1) {
            p0 += __shfl_xor_sync(0xffffffffu, p0, o);
            p1 += __shfl_xor_sync(0xffffffffu, p1, o);
            p2 += __shfl_xor_sync(0xffffffffu, p2, o);
        }

        if (s == 0) {
            // two smallest of three + min
            const float mn  = fminf(fminf(p0, p1), p2);
            const float mx  = fmaxf(fmaxf(p0, p1), p2);
            const float mid = (p0 + p1 + p2) - mn - mx;

            const float a = mn  + EPS_F;
            const float b = mid + EPS_F;
            // fast-math: 1 MUFU.RCP-based divide + 2 MUFU.LG2
            const float p = __fdividef(a, a + b);         // 0 < p <= 0.5
            const float ent = -(p * __log2f(p) + (1.f - p) * __log2f(1.f - p));

            acc_min += mn;
            if (ent <= TH_F) { acc_msk += mn; acc_cnt += 1.f; }
        }
    }

    // Warp reduce (only s==0 lanes carry nonzero values)
    #pragma unroll
    for (int o = 16; o > 0; o >>= 1) {
        acc_min += __shfl_xor_sync(0xffffffffu, acc_min, o);
        acc_msk += __shfl_xor_sync(0xffffffffu, acc_msk, o);
        acc_cnt += __shfl_xor_sync(0xffffffffu, acc_cnt, o);
    }

    // Block reduce + one double atomic triple per block
    __shared__ float sm[3][8];
    __shared__ bool  s_last;
    const int wib = threadIdx.x >> 5;
    if (lane == 0) { sm[0][wib] = acc_min; sm[1][wib] = acc_msk; sm[2][wib] = acc_cnt; }
    __syncthreads();

    if (threadIdx.x == 0) {
        float a = 0.f, b = 0.f, c = 0.f;
        #pragma unroll
        for (int i = 0; i < 8; i++) { a += sm[0][i]; b += sm[1][i]; c += sm[2][i]; }
        atomicAdd(&g_sum_min,    (double)a);
        atomicAdd(&g_sum_masked, (double)b);
        atomicAdd(&g_cnt,        (double)c);
        __threadfence();
        const unsigned int ticket = atomicAdd(&g_done, 1u);
        s_last = (ticket == (unsigned int)(GRID - 1));
    }
    __syncthreads();

    // Last block: produce outputs and reset state for the next graph replay
    if (s_last && threadIdx.x == 0) {
        __threadfence();
        const double smn = g_sum_min;
        const double smk = g_sum_masked;
        const double cnt = g_cnt;
        out[0] = (float)(smn / (double)BN);
        out[1] = (float)(smk / cnt);
        g_sum_min = 0.0; g_sum_masked = 0.0; g_cnt = 0.0;
        __threadfence();
        g_done = 0u;
    }
}

extern "C" void kernel_launch(void* const* d_in, const int* in_sizes, int n_in,
                              void* d_out, int out_size) {
    const float* x       = (const float*)d_in[0];   // [B, D] f32
    const int*   labels  = (const int*)  d_in[1];   // [B] i32
    const float* centers = (const float*)d_in[2];   // [C, K, D] f32

    dist_kernel<<<GRID, 256>>>((const float4*)x, labels,
                               (const float4*)centers, (float*)d_out);
}